// round 1
// baseline (speedup 1.0000x reference)
#include <cuda_runtime.h>
#include <math.h>

#define DD 4096
#define SS 128
#define NK 15
#define TT (SS*NK)   // 1920 evaluation points

// Scratch (static device arrays; allocation inside kernel_launch is forbidden)
__device__ float g_phi[TT * DD];   // sin(t*freqs)
__device__ float g_G  [TT * DD];   // cotangent * sech^2

__constant__ float c_nodes[NK] = {
    0.20778495500789848f, 0.4058451513773972f, 0.5860872354676911f,
    0.7415311855993945f,  0.8648644233597691f, 0.9491079123427585f,
    0.9914553711208126f, -0.9914553711208126f, -0.9491079123427585f,
   -0.8648644233597691f, -0.7415311855993945f, -0.5860872354676911f,
   -0.4058451513773972f, -0.20778495500789848f, 0.0f
};
__constant__ float c_wk[NK] = {
    0.20443294007529889f, 0.19035057806478542f, 0.1690047266392679f,
    0.14065325971552592f, 0.10479001032225019f, 0.06309209262997856f,
    0.022935322010529224f, 0.022935322010529224f, 0.06309209262997856f,
    0.10479001032225019f, 0.14065325971552592f, 0.1690047266392679f,
    0.19035057806478542f, 0.20443294007529889f, 0.20948214108472782f
};

// t for evaluation point n (replicates reference f32 arithmetic)
__device__ __forceinline__ void node_params(int n, float* tval, float* hwk) {
    int s = n / NK;
    int k = n - s * NK;
    float a = (float)s       * (1.0f/128.0f);
    float b = (float)(s + 1) * (1.0f/128.0f);
    float h = 0.5f * (b - a);
    float c = 0.5f * (a + b);
    *tval = c + h * c_nodes[k];
    *hwk  = h * c_wk[k];
}

// ---------------------------------------------------------------------------
// Stage 1: Phi[n][d] = sin(t[n] * freqs[d])
// ---------------------------------------------------------------------------
__global__ __launch_bounds__(256) void phi_kernel(const float* __restrict__ freqs) {
    int n = blockIdx.x;
    float tval, hwk;
    node_params(n, &tval, &hwk);
    float* row = g_phi + (size_t)n * DD;
    for (int j = threadIdx.x; j < DD; j += 256)
        row[j] = sinf(tval * freqs[j]);
}

// ---------------------------------------------------------------------------
// Stage 2: Z = Phi(1920x4096) @ W(4096x4096); G = hwk*cos(t*afreqs)*(1-tanh(Z+b)^2)
// 128x128x8 tile, 256 threads, 8x8 per thread (split 4+4 rows/cols, conflict-free)
// ---------------------------------------------------------------------------
__global__ __launch_bounds__(256) void gemm1_kernel(const float* __restrict__ W,
                                                    const float* __restrict__ bvec,
                                                    const float* __restrict__ afreqs) {
    __shared__ float As[8][128];   // [k][m]
    __shared__ float Bs[8][128];   // [k][n]
    const int tid  = threadIdx.x;
    const int brow = blockIdx.y;   // 0..14  (M = 1920 = 15*128)
    const int bcol = blockIdx.x;   // 0..31  (N = 4096)
    const int K = DD, N = DD;

    // A tile load: each thread one float4 (128x8 = 1024 floats / 256 thr)
    const int arow = tid >> 1;            // 0..127
    const int acol = (tid & 1) * 4;       // 0 or 4
    // B tile load: 8x128
    const int brl  = tid >> 5;            // 0..7
    const int bcl  = (tid & 31) * 4;      // 0..124

    const float* Aptr = g_phi + ((size_t)(brow*128 + arow)) * K + acol;
    const float* Bptr = W + (size_t)brl * N + bcol*128 + bcl;

    float acc[8][8];
    #pragma unroll
    for (int i = 0; i < 8; i++)
        #pragma unroll
        for (int j = 0; j < 8; j++) acc[i][j] = 0.0f;

    const int ty = tid >> 4, tx = tid & 15;

    for (int k0 = 0; k0 < K; k0 += 8) {
        float4 av = *(const float4*)(Aptr + k0);
        As[acol+0][arow] = av.x;
        As[acol+1][arow] = av.y;
        As[acol+2][arow] = av.z;
        As[acol+3][arow] = av.w;
        *(float4*)&Bs[brl][bcl] = *(const float4*)(Bptr + (size_t)k0 * N);
        __syncthreads();

        #pragma unroll
        for (int kk = 0; kk < 8; kk++) {
            float ar[8], br[8];
            *(float4*)&ar[0] = *(const float4*)&As[kk][ty*4];
            *(float4*)&ar[4] = *(const float4*)&As[kk][64 + ty*4];
            *(float4*)&br[0] = *(const float4*)&Bs[kk][tx*4];
            *(float4*)&br[4] = *(const float4*)&Bs[kk][64 + tx*4];
            #pragma unroll
            for (int i = 0; i < 8; i++)
                #pragma unroll
                for (int j = 0; j < 8; j++)
                    acc[i][j] += ar[i] * br[j];
        }
        __syncthreads();
    }

    // Fused epilogue -> g_G
    #pragma unroll
    for (int i = 0; i < 8; i++) {
        int rloc = (i < 4) ? (ty*4 + i) : (64 + ty*4 + (i - 4));
        int n = brow*128 + rloc;
        float tval, hwk;
        node_params(n, &tval, &hwk);
        #pragma unroll
        for (int jo = 0; jo < 2; jo++) {
            int cbase = bcol*128 + jo*64 + tx*4;
            float4 out4;
            float* o = (float*)&out4;
            #pragma unroll
            for (int j = 0; j < 4; j++) {
                int col = cbase + j;
                float z = acc[i][jo*4 + j] + bvec[col];
                float y = tanhf(z);
                o[j] = hwk * cosf(tval * afreqs[col]) * (1.0f - y*y);
            }
            *(float4*)&g_G[(size_t)n * DD + cbase] = out4;
        }
    }
}

// ---------------------------------------------------------------------------
// Stage 3: Out = Phi^T (4096x1920) @ G (1920x4096)
// Both operands are row-major [n][d]; tile loads are plain row slices.
// ---------------------------------------------------------------------------
__global__ __launch_bounds__(256) void gemm2_kernel(float* __restrict__ Out) {
    __shared__ float As[8][128];   // [k][m] : Phi[k0+k][brow*128 + m]
    __shared__ float Bs[8][128];   // [k][n] : G  [k0+k][bcol*128 + n]
    const int tid  = threadIdx.x;
    const int brow = blockIdx.y;   // 0..31
    const int bcol = blockIdx.x;   // 0..31
    const int K = TT;

    const int r  = tid >> 5;        // 0..7
    const int cq = (tid & 31) * 4;  // 0..124

    const float* Aptr = g_phi + (size_t)r * DD + brow*128 + cq;
    const float* Bptr = g_G   + (size_t)r * DD + bcol*128 + cq;

    float acc[8][8];
    #pragma unroll
    for (int i = 0; i < 8; i++)
        #pragma unroll
        for (int j = 0; j < 8; j++) acc[i][j] = 0.0f;

    const int ty = tid >> 4, tx = tid & 15;

    for (int k0 = 0; k0 < K; k0 += 8) {
        *(float4*)&As[r][cq] = *(const float4*)(Aptr + (size_t)k0 * DD);
        *(float4*)&Bs[r][cq] = *(const float4*)(Bptr + (size_t)k0 * DD);
        __syncthreads();

        #pragma unroll
        for (int kk = 0; kk < 8; kk++) {
            float ar[8], br[8];
            *(float4*)&ar[0] = *(const float4*)&As[kk][ty*4];
            *(float4*)&ar[4] = *(const float4*)&As[kk][64 + ty*4];
            *(float4*)&br[0] = *(const float4*)&Bs[kk][tx*4];
            *(float4*)&br[4] = *(const float4*)&Bs[kk][64 + tx*4];
            #pragma unroll
            for (int i = 0; i < 8; i++)
                #pragma unroll
                for (int j = 0; j < 8; j++)
                    acc[i][j] += ar[i] * br[j];
        }
        __syncthreads();
    }

    #pragma unroll
    for (int i = 0; i < 8; i++) {
        int rloc = (i < 4) ? (ty*4 + i) : (64 + ty*4 + (i - 4));
        int row = brow*128 + rloc;
        #pragma unroll
        for (int jo = 0; jo < 2; jo++) {
            int cbase = bcol*128 + jo*64 + tx*4;
            float4 v;
            v.x = acc[i][jo*4 + 0];
            v.y = acc[i][jo*4 + 1];
            v.z = acc[i][jo*4 + 2];
            v.w = acc[i][jo*4 + 3];
            *(float4*)&Out[(size_t)row * DD + cbase] = v;
        }
    }
}

// ---------------------------------------------------------------------------
extern "C" void kernel_launch(void* const* d_in, const int* in_sizes, int n_in,
                              void* d_out, int out_size) {
    const float* W      = (const float*)d_in[0];   // 4096*4096
    const float* b      = (const float*)d_in[1];   // 4096
    const float* freqs  = (const float*)d_in[2];   // 4096
    const float* afreqs = (const float*)d_in[3];   // 4096
    float* Out = (float*)d_out;                    // 4096*4096

    phi_kernel<<<TT, 256>>>(freqs);
    gemm1_kernel<<<dim3(32, 15), 256>>>(W, b, afreqs);
    gemm2_kernel<<<dim3(32, 32), 256>>>(Out);
}

// round 3
// speedup vs baseline: 2.0905x; 2.0905x over previous
#include <cuda_runtime.h>
#include <cuda_bf16.h>
#include <cstdint>
#include <math.h>

#define DD 4096
#define SS 128
#define NK 15
#define TT (SS*NK)   // 1920 evaluation points

// ---------------------------------------------------------------------------
// Scratch (static device arrays; no allocation allowed)
// ---------------------------------------------------------------------------
__device__ __align__(16) __nv_bfloat16 g_PhiA_h[(size_t)TT * DD];  // Phi   [np][d] hi
__device__ __align__(16) __nv_bfloat16 g_PhiA_l[(size_t)TT * DD];
__device__ __align__(16) __nv_bfloat16 g_PhiT_h[(size_t)DD * TT];  // Phi^T [d][np] hi
__device__ __align__(16) __nv_bfloat16 g_PhiT_l[(size_t)DD * TT];
__device__ __align__(16) __nv_bfloat16 g_WT_h [(size_t)DD * DD];   // W^T   [n][k]  hi
__device__ __align__(16) __nv_bfloat16 g_WT_l [(size_t)DD * DD];
__device__ __align__(16) __nv_bfloat16 g_GT_h [(size_t)DD * TT];   // G^T   [d][np] hi
__device__ __align__(16) __nv_bfloat16 g_GT_l [(size_t)DD * TT];

__constant__ float c_nodes[NK] = {
    0.20778495500789848f, 0.4058451513773972f, 0.5860872354676911f,
    0.7415311855993945f,  0.8648644233597691f, 0.9491079123427585f,
    0.9914553711208126f, -0.9914553711208126f, -0.9491079123427585f,
   -0.8648644233597691f, -0.7415311855993945f, -0.5860872354676911f,
   -0.4058451513773972f, -0.20778495500789848f, 0.0f
};
__constant__ float c_wk[NK] = {
    0.20443294007529889f, 0.19035057806478542f, 0.1690047266392679f,
    0.14065325971552592f, 0.10479001032225019f, 0.06309209262997856f,
    0.022935322010529224f, 0.022935322010529224f, 0.06309209262997856f,
    0.10479001032225019f, 0.14065325971552592f, 0.1690047266392679f,
    0.19035057806478542f, 0.20443294007529889f, 0.20948214108472782f
};

__device__ __forceinline__ void node_params(int n, float* tval, float* hwk) {
    int s = n / NK;
    int k = n - s * NK;
    float a = (float)s       * (1.0f/128.0f);
    float b = (float)(s + 1) * (1.0f/128.0f);
    float h = 0.5f * (b - a);
    float c = 0.5f * (a + b);
    *tval = c + h * c_nodes[k];
    *hwk  = h * c_wk[k];
}

__device__ __forceinline__ void split2(float x, __nv_bfloat16& h, __nv_bfloat16& l) {
    h = __float2bfloat16_rn(x);
    l = __float2bfloat16_rn(x - __bfloat162float(h));
}

__device__ __forceinline__ uint32_t smem_u32(const void* p) {
    uint32_t a;
    asm("{ .reg .u64 t; cvta.to.shared.u64 t, %1; cvt.u32.u64 %0, t; }" : "=r"(a) : "l"(p));
    return a;
}

__device__ __forceinline__ void cp16(uint32_t saddr, const void* g) {
    asm volatile("cp.async.cg.shared.global [%0], [%1], 16;\n" :: "r"(saddr), "l"(g) : "memory");
}
__device__ __forceinline__ void cp_commit() { asm volatile("cp.async.commit_group;\n" ::: "memory"); }
template<int N>
__device__ __forceinline__ void cp_wait() { asm volatile("cp.async.wait_group %0;\n" :: "n"(N) : "memory"); }

__device__ __forceinline__ void ldsm4(uint32_t* r, uint32_t addr) {
    asm volatile("ldmatrix.sync.aligned.m8n8.x4.shared.b16 {%0,%1,%2,%3}, [%4];"
        : "=r"(r[0]), "=r"(r[1]), "=r"(r[2]), "=r"(r[3]) : "r"(addr));
}

__device__ __forceinline__ void mma_bf16(float* c, const uint32_t* a, uint32_t b0, uint32_t b1) {
    asm volatile(
        "mma.sync.aligned.m16n8k16.row.col.f32.bf16.bf16.f32 "
        "{%0,%1,%2,%3}, {%4,%5,%6,%7}, {%8,%9}, {%0,%1,%2,%3};"
        : "+f"(c[0]), "+f"(c[1]), "+f"(c[2]), "+f"(c[3])
        : "r"(a[0]), "r"(a[1]), "r"(a[2]), "r"(a[3]), "r"(b0), "r"(b1));
}

// ---------------------------------------------------------------------------
// Stage 1 prep kernels
// ---------------------------------------------------------------------------
__global__ __launch_bounds__(256) void phiA_kernel(const float* __restrict__ freqs) {
    int n = blockIdx.x;
    float tval, hwk; node_params(n, &tval, &hwk);
    size_t base = (size_t)n * DD;
    for (int d = threadIdx.x; d < DD; d += 256) {
        float s = sinf(tval * freqs[d]);
        __nv_bfloat16 h, l; split2(s, h, l);
        g_PhiA_h[base + d] = h;
        g_PhiA_l[base + d] = l;
    }
}

__global__ __launch_bounds__(256) void phiT_kernel(const float* __restrict__ freqs) {
    int d = blockIdx.x;
    float f = freqs[d];
    size_t base = (size_t)d * TT;
    for (int n = threadIdx.x; n < TT; n += 256) {
        float tval, hwk; node_params(n, &tval, &hwk);
        float s = sinf(tval * f);
        __nv_bfloat16 h, l; split2(s, h, l);
        g_PhiT_h[base + n] = h;
        g_PhiT_l[base + n] = l;
    }
}

__global__ __launch_bounds__(256) void wt_kernel(const float* __restrict__ W) {
    __shared__ float t[32][33];
    int k0 = blockIdx.x * 32, n0 = blockIdx.y * 32;
    int tx = threadIdx.x & 31, ty = threadIdx.x >> 5;
    for (int i = ty; i < 32; i += 8)
        t[i][tx] = W[(size_t)(k0 + i) * DD + n0 + tx];
    __syncthreads();
    for (int i = ty; i < 32; i += 8) {
        float v = t[tx][i];                          // W[k0+tx][n0+i]
        size_t o = (size_t)(n0 + i) * DD + k0 + tx;  // WT[n][k]
        __nv_bfloat16 h, l; split2(v, h, l);
        g_WT_h[o] = h;
        g_WT_l[o] = l;
    }
}

// ---------------------------------------------------------------------------
// HMMA GEMM: D(128x256, fp32) = A(128xK) * B(256xK)^T, bf16 hi/lo 3-term split.
// MODE 1: A=Phi, B=WT -> epilogue writes GT (bf16 split).
// MODE 2: A=PhiT, B=GT -> Out (fp32).
// ---------------------------------------------------------------------------
#define BK 32
#define NSTAGE 3
#define A_BYTES (128*BK*2)     // 8192
#define B_BYTES (256*BK*2)     // 16384
#define STAGE_BYTES (2*A_BYTES + 2*B_BYTES)   // 49152
#define SMEM_TOTAL (NSTAGE * STAGE_BYTES)     // 147456
// stage layout: Ah [0,8K) Al [8K,16K) Bh [16K,32K) Bl [32K,48K)
#define AL_OFF  8192
#define BH_OFF  16384
#define BL_OFF  32768

// 16B-segment swizzle: row has 4 segs (64B), phys = seg ^ ((row>>1)&3)
__device__ __forceinline__ uint32_t swz(int row, int seg) {
    return (uint32_t)(row * 64 + ((seg ^ ((row >> 1) & 3)) << 4));
}

__device__ __forceinline__ void load_chunk(
    const __nv_bfloat16* __restrict__ Ah, const __nv_bfloat16* __restrict__ Al,
    const __nv_bfloat16* __restrict__ Bh, const __nv_bfloat16* __restrict__ Bl,
    int K, int m0, int n0, int k0, uint32_t stage, int tid)
{
    // 3072 cp16 ops: [0,1024) A (h,l), [1024,3072) B (h,l)
    #pragma unroll
    for (int it = 0; it < 12; it++) {
        int u = tid + it * 256;
        uint32_t dst; const __nv_bfloat16* src;
        if (u < 1024) {
            int buf = u >> 9;           // 0=h 1=l
            int v = u & 511;
            int row = v >> 2, seg = v & 3;
            dst = stage + buf * AL_OFF + swz(row, seg);
            const __nv_bfloat16* A = buf ? Al : Ah;
            src = A + (size_t)(m0 + row) * K + k0 + seg * 8;
        } else {
            int w = u - 1024;
            int buf = w >> 10;
            int v = w & 1023;
            int row = v >> 2, seg = v & 3;
            dst = stage + BH_OFF + buf * B_BYTES + swz(row, seg);
            const __nv_bfloat16* B = buf ? Bl : Bh;
            src = B + (size_t)(n0 + row) * K + k0 + seg * 8;
        }
        cp16(dst, src);
    }
    cp_commit();
}

template<int MODE>
__global__ void __launch_bounds__(256, 1) gemm_kernel(
    const float* __restrict__ bvec, const float* __restrict__ afreqs,
    float* __restrict__ Out)
{
    extern __shared__ char smem[];
    const uint32_t sb = smem_u32(smem);
    const int tid  = threadIdx.x;
    const int wid  = tid >> 5;
    const int lane = tid & 31;
    const int warpm = wid & 1;          // 2 m-blocks of 64
    const int warpn = wid >> 1;         // 4 n-blocks of 64
    const int g  = lane >> 2;
    const int t4 = lane & 3;

    const int K   = (MODE == 1) ? DD : TT;
    const int nch = K / BK;
    const int m0  = blockIdx.y * 128;
    const int n0  = blockIdx.x * 256;

    const __nv_bfloat16* Ah = (MODE == 1) ? g_PhiA_h : g_PhiT_h;
    const __nv_bfloat16* Al = (MODE == 1) ? g_PhiA_l : g_PhiT_l;
    const __nv_bfloat16* Bh = (MODE == 1) ? g_WT_h   : g_GT_h;
    const __nv_bfloat16* Bl = (MODE == 1) ? g_WT_l   : g_GT_l;

    float acc[4][8][4];
    #pragma unroll
    for (int i = 0; i < 4; i++)
        #pragma unroll
        for (int j = 0; j < 8; j++)
            #pragma unroll
            for (int r = 0; r < 4; r++) acc[i][j][r] = 0.0f;

    // prologue
    load_chunk(Ah, Al, Bh, Bl, K, m0, n0, 0, sb, tid);
    load_chunk(Ah, Al, Bh, Bl, K, m0, n0, BK, sb + STAGE_BYTES, tid);

    // precompute ldmatrix lane addressing (relative to stage base)
    // A: row = warpm*64 + fm*16 + (lane&15), seg = j*2 + (lane>>4)
    const int a_row_l = warpm * 64 + (lane & 15);
    const int a_hiseg = lane >> 4;
    // B: row = warpn*64 + fn2*16 + ((lane>>4)<<3) + (lane&7), seg = j*2 + ((lane>>3)&1)
    const int b_row_l = warpn * 64 + ((lane >> 4) << 3) + (lane & 7);
    const int b_hiseg = (lane >> 3) & 1;

    for (int i = 0; i < nch; i++) {
        if (i + 2 < nch) cp_wait<1>(); else cp_wait<0>();
        __syncthreads();
        if (i + 2 < nch)
            load_chunk(Ah, Al, Bh, Bl, K, m0, n0, (i + 2) * BK,
                       sb + ((i + 2) % NSTAGE) * STAGE_BYTES, tid);

        const uint32_t st = sb + (i % NSTAGE) * STAGE_BYTES;
        #pragma unroll
        for (int j = 0; j < 2; j++) {
            uint32_t ah[4][4], al[4][4], bh[4][4], bl[4][4];
            #pragma unroll
            for (int fm = 0; fm < 4; fm++) {
                int row = a_row_l + fm * 16;
                int seg = j * 2 + a_hiseg;
                uint32_t off = swz(row, seg);
                ldsm4(ah[fm], st + off);
                ldsm4(al[fm], st + AL_OFF + off);
            }
            #pragma unroll
            for (int fn = 0; fn < 4; fn++) {
                int row = b_row_l + fn * 16;
                int seg = j * 2 + b_hiseg;
                uint32_t off = swz(row, seg);
                ldsm4(bh[fn], st + BH_OFF + off);
                ldsm4(bl[fn], st + BL_OFF + off);
            }
            #pragma unroll
            for (int fm = 0; fm < 4; fm++)
                #pragma unroll
                for (int fn = 0; fn < 4; fn++) {
                    #pragma unroll
                    for (int h = 0; h < 2; h++) {
                        float* c = acc[fm][fn * 2 + h];
                        mma_bf16(c, ah[fm], bh[fn][h*2], bh[fn][h*2+1]);
                        mma_bf16(c, ah[fm], bl[fn][h*2], bl[fn][h*2+1]);
                        mma_bf16(c, al[fm], bh[fn][h*2], bh[fn][h*2+1]);
                    }
                }
        }
        __syncthreads();   // protect stage reuse
    }

    // -------------------- epilogue --------------------
    if (MODE == 2) {
        #pragma unroll
        for (int fm = 0; fm < 4; fm++) {
            #pragma unroll
            for (int h8 = 0; h8 < 2; h8++) {
                int d1 = m0 + warpm * 64 + fm * 16 + g + h8 * 8;
                float* orow = Out + (size_t)d1 * DD + n0 + warpn * 64 + t4 * 2;
                #pragma unroll
                for (int fn = 0; fn < 8; fn++) {
                    float2 v;
                    v.x = acc[fm][fn][h8 * 2 + 0];
                    v.y = acc[fm][fn][h8 * 2 + 1];
                    *(float2*)(orow + fn * 8) = v;
                }
            }
        }
        return;
    }

    // MODE 1: g = hwk * cos(t*afreq) * (1 - tanh(z+b)^2); write GT hi/lo
    // staging: S[128][264] bf16 (row stride 528B)
    float tv[8], hw[8];
    #pragma unroll
    for (int fm = 0; fm < 4; fm++)
        #pragma unroll
        for (int h8 = 0; h8 < 2; h8++) {
            int np = m0 + warpm * 64 + fm * 16 + g + h8 * 8;
            node_params(np, &tv[fm * 2 + h8], &hw[fm * 2 + h8]);
        }

    __syncthreads();
    #pragma unroll
    for (int pass = 0; pass < 2; pass++) {
        // compute + stage
        #pragma unroll
        for (int fm = 0; fm < 4; fm++) {
            #pragma unroll
            for (int h8 = 0; h8 < 2; h8++) {
                int np_loc = warpm * 64 + fm * 16 + g + h8 * 8;
                float tval = tv[fm * 2 + h8], hwk = hw[fm * 2 + h8];
                #pragma unroll
                for (int fn = 0; fn < 8; fn++) {
                    int d_loc = warpn * 64 + fn * 8 + t4 * 2;
                    int d = n0 + d_loc;
                    float z0 = acc[fm][fn][h8 * 2 + 0] + bvec[d];
                    float z1 = acc[fm][fn][h8 * 2 + 1] + bvec[d + 1];
                    float y0 = tanhf(z0), y1 = tanhf(z1);
                    float g0 = hwk * cosf(tval * afreqs[d])     * (1.0f - y0 * y0);
                    float g1 = hwk * cosf(tval * afreqs[d + 1]) * (1.0f - y1 * y1);
                    __nv_bfloat16 h0, l0, h1, l1;
                    split2(g0, h0, l0);
                    split2(g1, h1, l1);
                    __nv_bfloat162 v;
                    if (pass == 0) { v.x = h0; v.y = h1; } else { v.x = l0; v.y = l1; }
                    *(__nv_bfloat162*)(smem + np_loc * 528 + d_loc * 2) = v;
                }
            }
        }
        __syncthreads();
        // copy out transposed: each thread owns one d (0..255)
        {
            __nv_bfloat16* GT = pass ? g_GT_l : g_GT_h;
            int d = tid;
            __nv_bfloat16* grow = GT + (size_t)(n0 + d) * TT + m0;
            #pragma unroll
            for (int c = 0; c < 16; c++) {
                __nv_bfloat16 vals[8];
                #pragma unroll
                for (int q = 0; q < 8; q++)
                    vals[q] = *(__nv_bfloat16*)(smem + (c * 8 + q) * 528 + d * 2);
                *(uint4*)(grow + c * 8) = *(uint4*)vals;
            }
        }
        __syncthreads();
    }
}

// ---------------------------------------------------------------------------
extern "C" void kernel_launch(void* const* d_in, const int* in_sizes, int n_in,
                              void* d_out, int out_size) {
    const float* W      = (const float*)d_in[0];
    const float* b      = (const float*)d_in[1];
    const float* freqs  = (const float*)d_in[2];
    const float* afreqs = (const float*)d_in[3];
    float* Out = (float*)d_out;

    cudaFuncSetAttribute(gemm_kernel<1>, cudaFuncAttributeMaxDynamicSharedMemorySize, SMEM_TOTAL);
    cudaFuncSetAttribute(gemm_kernel<2>, cudaFuncAttributeMaxDynamicSharedMemorySize, SMEM_TOTAL);

    phiA_kernel<<<TT, 256>>>(freqs);
    phiT_kernel<<<DD, 256>>>(freqs);
    wt_kernel<<<dim3(DD/32, DD/32), 256>>>(W);

    // GEMM1: M=1920 (15), N=4096 (16 tiles of 256), K=4096
    gemm_kernel<1><<<dim3(16, 15), 256, SMEM_TOTAL>>>(b, afreqs, nullptr);
    // GEMM2: M=4096 (32), N=4096 (16), K=1920
    gemm_kernel<2><<<dim3(16, 32), 256, SMEM_TOTAL>>>(nullptr, nullptr, Out);
}

// round 4
// speedup vs baseline: 3.5371x; 1.6920x over previous
#include <cuda_runtime.h>
#include <cuda_fp16.h>
#include <cstdint>
#include <math.h>

#define DD 4096
#define SS 128
#define NK 15
#define TT (SS*NK)   // 1920 evaluation points

// ---------------------------------------------------------------------------
// Scratch (static device arrays; no allocation allowed)
// ---------------------------------------------------------------------------
__device__ __align__(16) __half g_PhiA_h[(size_t)TT * DD];  // Phi   [np][d] hi
__device__ __align__(16) __half g_PhiA_l[(size_t)TT * DD];  // Phi   [np][d] lo
__device__ __align__(16) __half g_PhiT_h[(size_t)DD * TT];  // Phi^T [d][np] hi
__device__ __align__(16) __half g_PhiT_l[(size_t)DD * TT];
__device__ __align__(16) __half g_WT  [(size_t)DD * DD];    // W^T   [n][k]  (rounded)
__device__ __align__(16) __half g_GT  [(size_t)DD * TT];    // G^T   [d][np] (rounded)

__constant__ float c_nodes[NK] = {
    0.20778495500789848f, 0.4058451513773972f, 0.5860872354676911f,
    0.7415311855993945f,  0.8648644233597691f, 0.9491079123427585f,
    0.9914553711208126f, -0.9914553711208126f, -0.9491079123427585f,
   -0.8648644233597691f, -0.7415311855993945f, -0.5860872354676911f,
   -0.4058451513773972f, -0.20778495500789848f, 0.0f
};
__constant__ float c_wk[NK] = {
    0.20443294007529889f, 0.19035057806478542f, 0.1690047266392679f,
    0.14065325971552592f, 0.10479001032225019f, 0.06309209262997856f,
    0.022935322010529224f, 0.022935322010529224f, 0.06309209262997856f,
    0.10479001032225019f, 0.14065325971552592f, 0.1690047266392679f,
    0.19035057806478542f, 0.20443294007529889f, 0.20948214108472782f
};

__device__ __forceinline__ void node_params(int n, float* tval, float* hwk) {
    int s = n / NK;
    int k = n - s * NK;
    float a = (float)s       * (1.0f/128.0f);
    float b = (float)(s + 1) * (1.0f/128.0f);
    float h = 0.5f * (b - a);
    float c = 0.5f * (a + b);
    *tval = c + h * c_nodes[k];
    *hwk  = h * c_wk[k];
}

__device__ __forceinline__ void split2h(float x, __half& h, __half& l) {
    h = __float2half_rn(x);
    l = __float2half_rn(x - __half2float(h));
}

__device__ __forceinline__ uint32_t smem_u32(const void* p) {
    uint32_t a;
    asm("{ .reg .u64 t; cvta.to.shared.u64 t, %1; cvt.u32.u64 %0, t; }" : "=r"(a) : "l"(p));
    return a;
}

__device__ __forceinline__ void cp16(uint32_t saddr, const void* g) {
    asm volatile("cp.async.cg.shared.global [%0], [%1], 16;\n" :: "r"(saddr), "l"(g) : "memory");
}
__device__ __forceinline__ void cp_commit() { asm volatile("cp.async.commit_group;\n" ::: "memory"); }
template<int N>
__device__ __forceinline__ void cp_wait() { asm volatile("cp.async.wait_group %0;\n" :: "n"(N) : "memory"); }

__device__ __forceinline__ void ldsm4(uint32_t* r, uint32_t addr) {
    asm volatile("ldmatrix.sync.aligned.m8n8.x4.shared.b16 {%0,%1,%2,%3}, [%4];"
        : "=r"(r[0]), "=r"(r[1]), "=r"(r[2]), "=r"(r[3]) : "r"(addr));
}

__device__ __forceinline__ void mma_f16(float* c, const uint32_t* a, uint32_t b0, uint32_t b1) {
    asm volatile(
        "mma.sync.aligned.m16n8k16.row.col.f32.f16.f16.f32 "
        "{%0,%1,%2,%3}, {%4,%5,%6,%7}, {%8,%9}, {%0,%1,%2,%3};"
        : "+f"(c[0]), "+f"(c[1]), "+f"(c[2]), "+f"(c[3])
        : "r"(a[0]), "r"(a[1]), "r"(a[2]), "r"(a[3]), "r"(b0), "r"(b1));
}

// ---------------------------------------------------------------------------
// Stage 1 prep kernels
// ---------------------------------------------------------------------------
__global__ __launch_bounds__(256) void phiA_kernel(const float* __restrict__ freqs) {
    int n = blockIdx.x;
    float tval, hwk; node_params(n, &tval, &hwk);
    size_t base = (size_t)n * DD;
    for (int d = threadIdx.x; d < DD; d += 256) {
        float s = sinf(tval * freqs[d]);
        __half h, l; split2h(s, h, l);
        g_PhiA_h[base + d] = h;
        g_PhiA_l[base + d] = l;
    }
}

__global__ __launch_bounds__(256) void phiT_kernel(const float* __restrict__ freqs) {
    int d = blockIdx.x;
    float f = freqs[d];
    size_t base = (size_t)d * TT;
    for (int n = threadIdx.x; n < TT; n += 256) {
        float tval, hwk; node_params(n, &tval, &hwk);
        float s = sinf(tval * f);
        __half h, l; split2h(s, h, l);
        g_PhiT_h[base + n] = h;
        g_PhiT_l[base + n] = l;
    }
}

__global__ __launch_bounds__(256) void wt_kernel(const float* __restrict__ W) {
    __shared__ float t[32][33];
    int k0 = blockIdx.x * 32, n0 = blockIdx.y * 32;
    int tx = threadIdx.x & 31, ty = threadIdx.x >> 5;
    for (int i = ty; i < 32; i += 8)
        t[i][tx] = W[(size_t)(k0 + i) * DD + n0 + tx];
    __syncthreads();
    for (int i = ty; i < 32; i += 8) {
        float v = t[tx][i];                          // W[k0+tx][n0+i]
        g_WT[(size_t)(n0 + i) * DD + k0 + tx] = __float2half_rn(v);
    }
}

// ---------------------------------------------------------------------------
// HMMA GEMM: D(128x256, fp32) = A(128xK) * B(256xK)^T, fp16 2-term (A hi/lo, B rn)
// MODE 1: A=Phi, B=WT -> epilogue writes GT (fp16).
// MODE 2: A=PhiT, B=GT -> Out (fp32).
// 512 threads, 16 warps in 4m x 4n grid, warp tile 32x64.
// ---------------------------------------------------------------------------
#define BK 32
#define NSTAGE 3
#define A_BYTES (128*BK*2)     // 8192
#define B_BYTES (256*BK*2)     // 16384
#define STAGE_BYTES (2*A_BYTES + B_BYTES)     // 32768
#define SMEM_TOTAL (NSTAGE * STAGE_BYTES)     // 98304
#define AL_OFF  8192
#define B_OFF   16384

// 16B-segment swizzle: row has 4 segs (64B), phys = seg ^ ((row>>1)&3)
__device__ __forceinline__ uint32_t swz(int row, int seg) {
    return (uint32_t)(row * 64 + ((seg ^ ((row >> 1) & 3)) << 4));
}

__device__ __forceinline__ void load_chunk(
    const __half* __restrict__ Ah, const __half* __restrict__ Al,
    const __half* __restrict__ B,
    int K, int m0, int n0, int k0, uint32_t stage, int tid)
{
    // 2048 cp16 ops: [0,512) Ah, [512,1024) Al, [1024,2048) B
    #pragma unroll
    for (int it = 0; it < 4; it++) {
        int u = tid + it * 512;
        uint32_t dst; const __half* src;
        if (u < 1024) {
            int buf = u >> 9;              // 0=h 1=l
            int v = u & 511;
            int row = v >> 2, seg = v & 3;
            dst = stage + buf * AL_OFF + swz(row, seg);
            const __half* A = buf ? Al : Ah;
            src = A + (size_t)(m0 + row) * K + k0 + seg * 8;
        } else {
            int v = u - 1024;
            int row = v >> 2, seg = v & 3;
            dst = stage + B_OFF + swz(row, seg);
            src = B + (size_t)(n0 + row) * K + k0 + seg * 8;
        }
        cp16(dst, src);
    }
    cp_commit();
}

template<int MODE>
__global__ void __launch_bounds__(512, 1) gemm_kernel(
    const float* __restrict__ bvec, const float* __restrict__ afreqs,
    float* __restrict__ Out)
{
    extern __shared__ char smem[];
    const uint32_t sb = smem_u32(smem);
    const int tid  = threadIdx.x;
    const int wid  = tid >> 5;
    const int lane = tid & 31;
    const int warpm = wid & 3;          // 4 m-blocks of 32
    const int warpn = wid >> 2;         // 4 n-blocks of 64
    const int g  = lane >> 2;
    const int t4 = lane & 3;

    const int K   = (MODE == 1) ? DD : TT;
    const int nch = K / BK;
    const int m0  = blockIdx.y * 128;
    const int n0  = blockIdx.x * 256;

    const __half* Ah = (MODE == 1) ? g_PhiA_h : g_PhiT_h;
    const __half* Al = (MODE == 1) ? g_PhiA_l : g_PhiT_l;
    const __half* B  = (MODE == 1) ? g_WT     : g_GT;

    float acc[2][8][4];
    #pragma unroll
    for (int i = 0; i < 2; i++)
        #pragma unroll
        for (int j = 0; j < 8; j++)
            #pragma unroll
            for (int r = 0; r < 4; r++) acc[i][j][r] = 0.0f;

    // prologue
    load_chunk(Ah, Al, B, K, m0, n0, 0, sb, tid);
    load_chunk(Ah, Al, B, K, m0, n0, BK, sb + STAGE_BYTES, tid);

    // ldmatrix lane addressing (relative to stage base)
    const int a_row_l = warpm * 32 + (lane & 15);
    const int a_hiseg = lane >> 4;
    const int b_row_l = warpn * 64 + ((lane >> 4) << 3) + (lane & 7);
    const int b_hiseg = (lane >> 3) & 1;

    for (int i = 0; i < nch; i++) {
        if (i + 2 < nch) cp_wait<1>(); else cp_wait<0>();
        __syncthreads();
        if (i + 2 < nch)
            load_chunk(Ah, Al, B, K, m0, n0, (i + 2) * BK,
                       sb + ((i + 2) % NSTAGE) * STAGE_BYTES, tid);

        const uint32_t st = sb + (i % NSTAGE) * STAGE_BYTES;
        #pragma unroll
        for (int j = 0; j < 2; j++) {
            uint32_t ah[2][4], al[2][4];
            #pragma unroll
            for (int fm = 0; fm < 2; fm++) {
                int row = a_row_l + fm * 16;
                int seg = j * 2 + a_hiseg;
                uint32_t off = swz(row, seg);
                ldsm4(ah[fm], st + off);
                ldsm4(al[fm], st + AL_OFF + off);
            }
            #pragma unroll
            for (int fn = 0; fn < 4; fn++) {
                uint32_t b[4];
                {
                    int row = b_row_l + fn * 16;
                    int seg = j * 2 + b_hiseg;
                    ldsm4(b, st + B_OFF + swz(row, seg));
                }
                #pragma unroll
                for (int fm = 0; fm < 2; fm++)
                    #pragma unroll
                    for (int h = 0; h < 2; h++) {
                        float* c = acc[fm][fn * 2 + h];
                        mma_f16(c, ah[fm], b[h*2], b[h*2+1]);
                        mma_f16(c, al[fm], b[h*2], b[h*2+1]);
                    }
            }
        }
    }

    // -------------------- epilogue --------------------
    if (MODE == 2) {
        #pragma unroll
        for (int fm = 0; fm < 2; fm++) {
            #pragma unroll
            for (int h8 = 0; h8 < 2; h8++) {
                int d1 = m0 + warpm * 32 + fm * 16 + g + h8 * 8;
                float* orow = Out + (size_t)d1 * DD + n0 + warpn * 64 + t4 * 2;
                #pragma unroll
                for (int fn = 0; fn < 8; fn++) {
                    float2 v;
                    v.x = acc[fm][fn][h8 * 2 + 0];
                    v.y = acc[fm][fn][h8 * 2 + 1];
                    *(float2*)(orow + fn * 8) = v;
                }
            }
        }
        return;
    }

    // MODE 1: g = hwk * cos(t*afreq) * (1 - tanh(z+b)^2); write GT (fp16)
    // staging: S[128 np][264 d] fp16, row stride 528B
    float tv[4], hw[4];
    #pragma unroll
    for (int fm = 0; fm < 2; fm++)
        #pragma unroll
        for (int h8 = 0; h8 < 2; h8++) {
            int np = m0 + warpm * 32 + fm * 16 + g + h8 * 8;
            node_params(np, &tv[fm * 2 + h8], &hw[fm * 2 + h8]);
        }

    __syncthreads();   // all ldmatrix reads of last stage done before overwrite
    #pragma unroll
    for (int fm = 0; fm < 2; fm++) {
        #pragma unroll
        for (int h8 = 0; h8 < 2; h8++) {
            int np_loc = warpm * 32 + fm * 16 + g + h8 * 8;
            float tval = tv[fm * 2 + h8], hwk = hw[fm * 2 + h8];
            #pragma unroll
            for (int fn = 0; fn < 8; fn++) {
                int d_loc = warpn * 64 + fn * 8 + t4 * 2;
                int d = n0 + d_loc;
                float z0 = acc[fm][fn][h8 * 2 + 0] + bvec[d];
                float z1 = acc[fm][fn][h8 * 2 + 1] + bvec[d + 1];
                float y0 = tanhf(z0), y1 = tanhf(z1);
                float g0 = hwk * cosf(tval * afreqs[d])     * (1.0f - y0 * y0);
                float g1 = hwk * cosf(tval * afreqs[d + 1]) * (1.0f - y1 * y1);
                __half2 v;
                v.x = __float2half_rn(g0);
                v.y = __float2half_rn(g1);
                *(__half2*)(smem + np_loc * 528 + d_loc * 2) = v;
            }
        }
    }
    __syncthreads();
    // copy out transposed: thread t owns d = t>>1, np-range half (t&1)*64
    {
        int d = tid >> 1;
        int seg2 = tid & 1;
        __half* grow = g_GT + (size_t)(n0 + d) * TT + m0 + seg2 * 64;
        #pragma unroll
        for (int c = 0; c < 8; c++) {
            __half vals[8];
            #pragma unroll
            for (int q = 0; q < 8; q++)
                vals[q] = *(__half*)(smem + (seg2 * 64 + c * 8 + q) * 528 + d * 2);
            *(uint4*)(grow + c * 8) = *(uint4*)vals;
        }
    }
}

// ---------------------------------------------------------------------------
extern "C" void kernel_launch(void* const* d_in, const int* in_sizes, int n_in,
                              void* d_out, int out_size) {
    const float* W      = (const float*)d_in[0];
    const float* b      = (const float*)d_in[1];
    const float* freqs  = (const float*)d_in[2];
    const float* afreqs = (const float*)d_in[3];
    float* Out = (float*)d_out;

    cudaFuncSetAttribute(gemm_kernel<1>, cudaFuncAttributeMaxDynamicSharedMemorySize, SMEM_TOTAL);
    cudaFuncSetAttribute(gemm_kernel<2>, cudaFuncAttributeMaxDynamicSharedMemorySize, SMEM_TOTAL);

    phiA_kernel<<<TT, 256>>>(freqs);
    phiT_kernel<<<DD, 256>>>(freqs);
    wt_kernel<<<dim3(DD/32, DD/32), 256>>>(W);

    // GEMM1: M=1920 (15), N=4096 (16 tiles of 256), K=4096
    gemm_kernel<1><<<dim3(16, 15), 512, SMEM_TOTAL>>>(b, afreqs, nullptr);
    // GEMM2: M=4096 (32), N=4096 (16), K=1920
    gemm_kernel<2><<<dim3(16, 32), 512, SMEM_TOTAL>>>(nullptr, nullptr, Out);
}

// round 5
// speedup vs baseline: 6.4324x; 1.8185x over previous
#include <cuda_runtime.h>
#include <cuda_fp16.h>
#include <cstdint>
#include <math.h>

#define DD 4096
#define SS 128
#define NK 15
#define TT (SS*NK)   // 1920 evaluation points

// ---------------------------------------------------------------------------
// Scratch (static device arrays; no allocation allowed)
// ---------------------------------------------------------------------------
__device__ __align__(16) __half g_PhiA[(size_t)TT * DD];  // Phi   [np][d]
__device__ __align__(16) __half g_PhiT[(size_t)DD * TT];  // Phi^T [d][np]
__device__ __align__(16) __half g_WT [(size_t)DD * DD];   // W^T   [n][k]
__device__ __align__(16) __half g_GT [(size_t)DD * TT];   // G^T   [d][np]

__constant__ float c_nodes[NK] = {
    0.20778495500789848f, 0.4058451513773972f, 0.5860872354676911f,
    0.7415311855993945f,  0.8648644233597691f, 0.9491079123427585f,
    0.9914553711208126f, -0.9914553711208126f, -0.9491079123427585f,
   -0.8648644233597691f, -0.7415311855993945f, -0.5860872354676911f,
   -0.4058451513773972f, -0.20778495500789848f, 0.0f
};
__constant__ float c_wk[NK] = {
    0.20443294007529889f, 0.19035057806478542f, 0.1690047266392679f,
    0.14065325971552592f, 0.10479001032225019f, 0.06309209262997856f,
    0.022935322010529224f, 0.022935322010529224f, 0.06309209262997856f,
    0.10479001032225019f, 0.14065325971552592f, 0.1690047266392679f,
    0.19035057806478542f, 0.20443294007529889f, 0.20948214108472782f
};

__device__ __forceinline__ void node_params(int n, float* tval, float* hwk) {
    int s = n / NK;
    int k = n - s * NK;
    float a = (float)s       * (1.0f/128.0f);
    float b = (float)(s + 1) * (1.0f/128.0f);
    float h = 0.5f * (b - a);
    float c = 0.5f * (a + b);
    *tval = c + h * c_nodes[k];
    *hwk  = h * c_wk[k];
}

__device__ __forceinline__ uint32_t smem_u32(const void* p) {
    uint32_t a;
    asm("{ .reg .u64 t; cvta.to.shared.u64 t, %1; cvt.u32.u64 %0, t; }" : "=r"(a) : "l"(p));
    return a;
}

__device__ __forceinline__ void cp16(uint32_t saddr, const void* g) {
    asm volatile("cp.async.cg.shared.global [%0], [%1], 16;\n" :: "r"(saddr), "l"(g) : "memory");
}
__device__ __forceinline__ void cp_commit() { asm volatile("cp.async.commit_group;\n" ::: "memory"); }
template<int N>
__device__ __forceinline__ void cp_wait() { asm volatile("cp.async.wait_group %0;\n" :: "n"(N) : "memory"); }

__device__ __forceinline__ void ldsm4(uint32_t* r, uint32_t addr) {
    asm volatile("ldmatrix.sync.aligned.m8n8.x4.shared.b16 {%0,%1,%2,%3}, [%4];"
        : "=r"(r[0]), "=r"(r[1]), "=r"(r[2]), "=r"(r[3]) : "r"(addr));
}

__device__ __forceinline__ void mma_f16(float* c, const uint32_t* a, uint32_t b0, uint32_t b1) {
    asm volatile(
        "mma.sync.aligned.m16n8k16.row.col.f32.f16.f16.f32 "
        "{%0,%1,%2,%3}, {%4,%5,%6,%7}, {%8,%9}, {%0,%1,%2,%3};"
        : "+f"(c[0]), "+f"(c[1]), "+f"(c[2]), "+f"(c[3])
        : "r"(a[0]), "r"(a[1]), "r"(a[2]), "r"(a[3]), "r"(b0), "r"(b1));
}

// ---------------------------------------------------------------------------
// Stage 1 prep kernels
// ---------------------------------------------------------------------------
__global__ __launch_bounds__(256) void phiA_kernel(const float* __restrict__ freqs) {
    int n = blockIdx.x;
    float tval, hwk; node_params(n, &tval, &hwk);
    size_t base = (size_t)n * DD;
    for (int d = threadIdx.x; d < DD; d += 256)
        g_PhiA[base + d] = __float2half_rn(sinf(tval * freqs[d]));
}

__global__ __launch_bounds__(256) void phiT_kernel(const float* __restrict__ freqs) {
    int d = blockIdx.x;
    float f = freqs[d];
    size_t base = (size_t)d * TT;
    for (int n = threadIdx.x; n < TT; n += 256) {
        float tval, hwk; node_params(n, &tval, &hwk);
        g_PhiT[base + n] = __float2half_rn(sinf(tval * f));
    }
}

__global__ __launch_bounds__(256) void wt_kernel(const float* __restrict__ W) {
    __shared__ float t[32][33];
    int k0 = blockIdx.x * 32, n0 = blockIdx.y * 32;
    int tx = threadIdx.x & 31, ty = threadIdx.x >> 5;
    for (int i = ty; i < 32; i += 8)
        t[i][tx] = W[(size_t)(k0 + i) * DD + n0 + tx];
    __syncthreads();
    for (int i = ty; i < 32; i += 8)
        g_WT[(size_t)(n0 + i) * DD + k0 + tx] = __float2half_rn(t[tx][i]);
}

// ---------------------------------------------------------------------------
// HMMA GEMM: D(128x256, fp32) = A(128xK) * B(256xK)^T, fp16.
// MODE 1: A=Phi, B=WT -> epilogue writes GT (fp16).
// MODE 2: A=PhiT, B=GT -> Out (fp32).
// 512 threads, 16 warps in 4m x 4n grid, warp tile 32x64.
// BK=64, 4-stage cp.async pipeline.
// ---------------------------------------------------------------------------
#define BK 64
#define NSTAGE 4
#define A_BYTES (128*BK*2)     // 16384
#define B_BYTES (256*BK*2)     // 32768
#define STAGE_BYTES (A_BYTES + B_BYTES)       // 49152
#define SMEM_TOTAL (NSTAGE * STAGE_BYTES)     // 196608

// 128B rows, 8 x 16B segs; phys seg = seg ^ (row&7)  (SW128 pattern)
__device__ __forceinline__ uint32_t swz(int row, int seg) {
    return (uint32_t)(row * 128 + ((seg ^ (row & 7)) << 4));
}

__device__ __forceinline__ void load_chunk(
    const __half* __restrict__ A, const __half* __restrict__ B,
    int K, int m0, int n0, int k0, uint32_t stage, int tid)
{
    // 3072 cp16: [0,1024) A (128 rows x 8 segs), [1024,3072) B (256 rows x 8 segs)
    #pragma unroll
    for (int it = 0; it < 6; it++) {
        int u = tid + it * 512;
        uint32_t dst; const __half* src;
        if (u < 1024) {
            int row = u >> 3, seg = u & 7;
            dst = stage + swz(row, seg);
            src = A + (size_t)(m0 + row) * K + k0 + seg * 8;
        } else {
            int v = u - 1024;
            int row = v >> 3, seg = v & 7;
            dst = stage + A_BYTES + swz(row, seg);
            src = B + (size_t)(n0 + row) * K + k0 + seg * 8;
        }
        cp16(dst, src);
    }
    cp_commit();
}

template<int MODE>
__global__ void __launch_bounds__(512, 1) gemm_kernel(
    const float* __restrict__ bvec, const float* __restrict__ afreqs,
    float* __restrict__ Out)
{
    extern __shared__ char smem[];
    const uint32_t sb = smem_u32(smem);
    const int tid  = threadIdx.x;
    const int wid  = tid >> 5;
    const int lane = tid & 31;
    const int warpm = wid & 3;          // 4 m-blocks of 32
    const int warpn = wid >> 2;         // 4 n-blocks of 64
    const int g  = lane >> 2;
    const int t4 = lane & 3;

    const int K   = (MODE == 1) ? DD : TT;
    const int nch = K / BK;             // 64 or 30
    const int m0  = blockIdx.y * 128;
    const int n0  = blockIdx.x * 256;

    const __half* A = (MODE == 1) ? g_PhiA : g_PhiT;
    const __half* B = (MODE == 1) ? g_WT   : g_GT;

    float acc[2][8][4];
    #pragma unroll
    for (int i = 0; i < 2; i++)
        #pragma unroll
        for (int j = 0; j < 8; j++)
            #pragma unroll
            for (int r = 0; r < 4; r++) acc[i][j][r] = 0.0f;

    // prologue: 3-deep prefetch
    load_chunk(A, B, K, m0, n0, 0,      sb,                   tid);
    load_chunk(A, B, K, m0, n0, BK,     sb + STAGE_BYTES,     tid);
    load_chunk(A, B, K, m0, n0, 2 * BK, sb + 2 * STAGE_BYTES, tid);

    // ldmatrix lane addressing
    const int a_row_l = warpm * 32 + (lane & 15);
    const int a_hiseg = lane >> 4;
    const int b_row_l = warpn * 64 + ((lane >> 4) << 3) + (lane & 7);
    const int b_hiseg = (lane >> 3) & 1;

    for (int i = 0; i < nch; i++) {
        if (i <= nch - 3)      cp_wait<2>();
        else if (i == nch - 2) cp_wait<1>();
        else                   cp_wait<0>();
        __syncthreads();
        if (i + 3 < nch)
            load_chunk(A, B, K, m0, n0, (i + 3) * BK,
                       sb + ((i + 3) & 3) * STAGE_BYTES, tid);

        const uint32_t st = sb + (i & 3) * STAGE_BYTES;
        #pragma unroll
        for (int j = 0; j < 4; j++) {
            uint32_t ah[2][4];
            #pragma unroll
            for (int fm = 0; fm < 2; fm++) {
                int row = a_row_l + fm * 16;
                int seg = j * 2 + a_hiseg;
                ldsm4(ah[fm], st + swz(row, seg));
            }
            #pragma unroll
            for (int fn = 0; fn < 4; fn++) {
                uint32_t b[4];
                {
                    int row = b_row_l + fn * 16;
                    int seg = j * 2 + b_hiseg;
                    ldsm4(b, st + A_BYTES + swz(row, seg));
                }
                #pragma unroll
                for (int fm = 0; fm < 2; fm++)
                    #pragma unroll
                    for (int h = 0; h < 2; h++)
                        mma_f16(acc[fm][fn * 2 + h], ah[fm], b[h*2], b[h*2+1]);
            }
        }
    }

    // -------------------- epilogue --------------------
    if (MODE == 2) {
        #pragma unroll
        for (int fm = 0; fm < 2; fm++) {
            #pragma unroll
            for (int h8 = 0; h8 < 2; h8++) {
                int d1 = m0 + warpm * 32 + fm * 16 + g + h8 * 8;
                float* orow = Out + (size_t)d1 * DD + n0 + warpn * 64 + t4 * 2;
                #pragma unroll
                for (int fn = 0; fn < 8; fn++) {
                    float2 v;
                    v.x = acc[fm][fn][h8 * 2 + 0];
                    v.y = acc[fm][fn][h8 * 2 + 1];
                    *(float2*)(orow + fn * 8) = v;
                }
            }
        }
        return;
    }

    // MODE 1: g = hwk * cos(t*afreq) * (1 - tanh(z+b)^2); write GT (fp16)
    // staging: S[128 np][264 d] fp16, row stride 528B
    float tv[4], hw[4];
    #pragma unroll
    for (int fm = 0; fm < 2; fm++)
        #pragma unroll
        for (int h8 = 0; h8 < 2; h8++) {
            int np = m0 + warpm * 32 + fm * 16 + g + h8 * 8;
            node_params(np, &tv[fm * 2 + h8], &hw[fm * 2 + h8]);
        }

    __syncthreads();   // all ldmatrix reads of last stage done before overwrite
    #pragma unroll
    for (int fm = 0; fm < 2; fm++) {
        #pragma unroll
        for (int h8 = 0; h8 < 2; h8++) {
            int np_loc = warpm * 32 + fm * 16 + g + h8 * 8;
            float tval = tv[fm * 2 + h8], hwk = hw[fm * 2 + h8];
            #pragma unroll
            for (int fn = 0; fn < 8; fn++) {
                int d_loc = warpn * 64 + fn * 8 + t4 * 2;
                int d = n0 + d_loc;
                float z0 = acc[fm][fn][h8 * 2 + 0] + bvec[d];
                float z1 = acc[fm][fn][h8 * 2 + 1] + bvec[d + 1];
                float y0 = tanhf(z0), y1 = tanhf(z1);
                float g0 = hwk * cosf(tval * afreqs[d])     * (1.0f - y0 * y0);
                float g1 = hwk * cosf(tval * afreqs[d + 1]) * (1.0f - y1 * y1);
                __half2 v;
                v.x = __float2half_rn(g0);
                v.y = __float2half_rn(g1);
                *(__half2*)(smem + np_loc * 528 + d_loc * 2) = v;
            }
        }
    }
    __syncthreads();
    // copy out transposed: thread t owns d = t>>1, np-range half (t&1)*64
    {
        int d = tid >> 1;
        int seg2 = tid & 1;
        __half* grow = g_GT + (size_t)(n0 + d) * TT + m0 + seg2 * 64;
        #pragma unroll
        for (int c = 0; c < 8; c++) {
            __half vals[8];
            #pragma unroll
            for (int q = 0; q < 8; q++)
                vals[q] = *(__half*)(smem + (seg2 * 64 + c * 8 + q) * 528 + d * 2);
            *(uint4*)(grow + c * 8) = *(uint4*)vals;
        }
    }
}

// ---------------------------------------------------------------------------
extern "C" void kernel_launch(void* const* d_in, const int* in_sizes, int n_in,
                              void* d_out, int out_size) {
    const float* W      = (const float*)d_in[0];
    const float* b      = (const float*)d_in[1];
    const float* freqs  = (const float*)d_in[2];
    const float* afreqs = (const float*)d_in[3];
    float* Out = (float*)d_out;

    cudaFuncSetAttribute(gemm_kernel<1>, cudaFuncAttributeMaxDynamicSharedMemorySize, SMEM_TOTAL);
    cudaFuncSetAttribute(gemm_kernel<2>, cudaFuncAttributeMaxDynamicSharedMemorySize, SMEM_TOTAL);

    phiA_kernel<<<TT, 256>>>(freqs);
    phiT_kernel<<<DD, 256>>>(freqs);
    wt_kernel<<<dim3(DD/32, DD/32), 256>>>(W);

    // GEMM1: M=1920 (15), N=4096 (16 tiles of 256), K=4096
    gemm_kernel<1><<<dim3(16, 15), 512, SMEM_TOTAL>>>(b, afreqs, nullptr);
    // GEMM2: M=4096 (32), N=4096 (16), K=1920
    gemm_kernel<2><<<dim3(16, 32), 512, SMEM_TOTAL>>>(nullptr, nullptr, Out);
}